// round 6
// baseline (speedup 1.0000x reference)
#include <cuda_runtime.h>

#define BB 8192
#define TT 2048
#define NTHREADS 128           // 4 warps/block -> 1 warp per SMSP
#define NBLOCKS  128           // 512 warps; 16 chains/warp (lane-pair per chain)
#define CHUNK 8                // timesteps per prefetch chunk

#define NL2E  (-1.4426950408889634f)   // -log2(e)
#define N2L2E (-2.8853900817779268f)   // -2*log2(e)

__device__ __forceinline__ float ex2_ap(float x) {
    float y;
    asm("ex2.approx.f32 %0, %1;" : "=f"(y) : "f"(x));
    return y;
}
__device__ __forceinline__ float rcp_ap(float x) {
    float y;
    asm("rcp.approx.f32 %0, %1;" : "=f"(y) : "f"(x));
    return y;
}

// Lane pair (2j, 2j+1) owns one chain; lane parity u owns hidden unit u.
// Activations via EX2+RCP (lat ~16 each) instead of MUFU.TANH (lat ~95):
//   sigma(z) = rcp(1 + ex2(-z*log2e))        [-log2e folded into weights]
//   tanh(g)  = 2*sigma(2g) - 1               [-2log2e folded into g rows]
//   tanh(c)  = 2*rcp(1 + ex2(c*N2L2E)) - 1
// Cuts per-step critical path from ~235 cyc to ~135.
__global__ void __launch_bounds__(NTHREADS, 1)
lstm_kernel(const float* __restrict__ x,
            const float* __restrict__ h0in,
            const float* __restrict__ c0in,
            const float* __restrict__ w_ih,
            const float* __restrict__ w_hh,
            const float* __restrict__ b_ih,
            const float* __restrict__ b_hh,
            float* __restrict__ out)
{
    const int tid  = blockIdx.x * NTHREADS + threadIdx.x;
    const int lane = threadIdx.x & 31;
    const int pair = tid >> 1;          // chain (batch element)
    const int u    = tid & 1;           // hidden unit owned by this lane

    // Gate rows (torch order): i=0+u, f=2+u, g=4+u, o=6+u.
    // Pre-scale: i,f,o rows by -log2e ; g row by -2log2e.
    float wi0[4], wi1[4], wh0[4], wh1[4], bs[4];   // q: 0=i,1=f,2=g,3=o
#pragma unroll
    for (int q = 0; q < 4; q++) {
        const int row = 2 * q + u;
        const float s = (q == 2) ? N2L2E : NL2E;
        wi0[q] = s * __ldg(&w_ih[2*row+0]);
        wi1[q] = s * __ldg(&w_ih[2*row+1]);
        wh0[q] = s * __ldg(&w_hh[2*row+0]);
        wh1[q] = s * __ldg(&w_hh[2*row+1]);
        bs[q]  = s * (__ldg(&b_ih[row]) + __ldg(&b_hh[row]));
    }

    float h_own = h0in[2*pair + u];
    float c     = c0in[2*pair + u];

    const float4* __restrict__ xr =
        reinterpret_cast<const float4*>(x) + (size_t)pair * (TT * 2 / 4);

    float4 buf[2][CHUNK / 2];
#pragma unroll
    for (int q = 0; q < CHUNK / 2; q++) buf[0][q] = __ldg(&xr[q]);

    const int lane_e = lane & ~1;
    const int lane_o = lane |  1;

#pragma unroll 1
    for (int ch = 0; ch < TT / CHUNK; ch++) {
        const int nb = (ch + 1) & 1;
        if (ch + 1 < TT / CHUNK) {
#pragma unroll
            for (int q = 0; q < CHUNK / 2; q++)
                buf[nb][q] = __ldg(&xr[(ch + 1) * (CHUNK / 2) + q]);
        }
#pragma unroll
        for (int s2 = 0; s2 < CHUNK / 2; s2++) {
            const float4 v = buf[ch & 1][s2];
#pragma unroll
            for (int half = 0; half < 2; half++) {
                const float x0 = half ? v.z : v.x;
                const float x1 = half ? v.w : v.y;

                // Exchange hidden state (both lanes get h0, h1).
                const float h_0 = __shfl_sync(0xffffffffu, h_own, lane_e);
                const float h_1 = __shfl_sync(0xffffffffu, h_own, lane_o);

                // z_q (already scaled by -log2e / -2log2e): x part hoistable,
                // h terms last -> only 2 fma deep from h.
                float z[4];
#pragma unroll
                for (int q = 0; q < 4; q++) {
                    float t = fmaf(x1, wi1[q], bs[q]);
                    t = fmaf(x0, wi0[q], t);
                    t = fmaf(h_1, wh1[q], t);
                    t = fmaf(h_0, wh0[q], t);
                    z[q] = t;
                }

                // Four independent EX2 -> +1 -> RCP chains (lat ~36 each,
                // running in parallel; MUFU pipe rt 8 per op).
                const float Ei = ex2_ap(z[0]);
                const float Ef = ex2_ap(z[1]);
                const float Eg = ex2_ap(z[2]);
                const float Eo = ex2_ap(z[3]);
                const float Ri = rcp_ap(Ei + 1.0f);   // sigma(i)
                const float Rf = rcp_ap(Ef + 1.0f);   // sigma(f)
                const float Rg = rcp_ap(Eg + 1.0f);   // (tanh(g)+1)/2
                const float Ro = rcp_ap(Eo + 1.0f);   // sigma(o)

                // c' = Rf*c + Ri*(2Rg - 1) = Rf*c - Ri + 2*Ri*Rg
                const float a  = fmaf(Rf, c, -Ri);
                const float bb = Ri * Rg;
                c = fmaf(2.0f, bb, a);

                // h' = sigma(o)*tanh(c') = 2*Ro*Rc - Ro,
                //      Rc = rcp(1 + ex2(c*N2L2E))
                const float two_so = Ro + Ro;          // off critical path
                const float m  = c * N2L2E;
                const float Ec = ex2_ap(m);
                const float Rc = rcp_ap(Ec + 1.0f);
                h_own = fmaf(two_so, Rc, -Ro);
            }
        }
    }

    out[2*pair + u] = c;
}

extern "C" void kernel_launch(void* const* d_in, const int* in_sizes, int n_in,
                              void* d_out, int out_size) {
    const float* x    = (const float*)d_in[0];
    const float* h0   = (const float*)d_in[1];
    const float* c0   = (const float*)d_in[2];
    const float* w_ih = (const float*)d_in[3];
    const float* w_hh = (const float*)d_in[4];
    const float* b_ih = (const float*)d_in[5];
    const float* b_hh = (const float*)d_in[6];
    lstm_kernel<<<NBLOCKS, NTHREADS>>>(x, h0, c0, w_ih, w_hh, b_ih, b_hh,
                                       (float*)d_out);
}

// round 7
// speedup vs baseline: 1.3630x; 1.3630x over previous
#include <cuda_runtime.h>

#define BB 8192
#define TT 2048
#define NTHREADS 128           // 4 warps/block -> 1 warp per SMSP
#define NBLOCKS  128           // 512 warps; lane pair per chain
#define CHUNK 8                // timesteps per prefetch chunk

#define MAGIC 12582912.0f      // 1.5 * 2^23: round-to-nearest-int trick
#define N2L2E (-2.8853900817779268f)   // -2*log2(e)  (cell-state scale)
#define NL2E  (-1.4426950408889634f)   // -log2(e)
#define INVS  (-0.34657359027997264f)  // 1/N2L2E = -ln2/2

__device__ __forceinline__ float tanh_ap(float x) {
    float y;
    asm("tanh.approx.f32 %0, %1;" : "=f"(y) : "f"(x));
    return y;
}

// r = 1/(1+2^zc) on the FMA/ALU pipes only (no MUFU): depth ~60 cyc of
// fixed-latency ops vs ~90 for a dependent MUFU. zc must be in [-60, 60].
__device__ __forceinline__ float sig2_fma(float zc) {
    // 2^zc = 2^rz * 2^f,  f in [-0.5, 0.5]
    const float tb = __fadd_rn(zc, MAGIC);        // low mantissa bits = round(zc)
    const float rz = __fsub_rn(tb, MAGIC);
    const float f  = __fsub_rn(zc, rz);
    // deg-5 poly for 2^f (Taylor in ln2 powers; trunc err ~2.4e-6 rel)
    const float f2 = f * f;
    const float pa = fmaf(0.0013333558f, f, 0.009618129f);
    const float pb = fmaf(0.055504109f,  f, 0.24022651f);
    const float pc = fmaf(0.69314718f,   f, 1.0f);
    const float q  = fmaf(pa, f2, pb);
    const float p  = fmaf(q,  f2, pc);
    // scale by 2^rz via exponent bit injection (wrap-safe for |zc|<=60)
    const int  ib = (__float_as_int(tb) << 23) + 0x3F800000;
    const float e = p * __int_as_float(ib);
    // 1/(1+e): bit-magic seed (~3.4e-2) + 2 Newton -> ~1.3e-6
    const float d  = e + 1.0f;
    float r = __int_as_float(0x7EF311C3 - __float_as_int(d));
    r = r * fmaf(-d, r, 2.0f);
    r = r * fmaf(-d, r, 2.0f);
    return r;
}

// Lane pair (2j, 2j+1) owns one chain; lane parity u owns hidden unit u.
// Gates on MUFU.TANH (sigma(z)=0.5 tanh(0.5 z)+0.5, 0.5 folded into weights).
// tanh(c) on the FMA pipe via sig2_fma, with cell state tracked pre-scaled:
//   cs = -2*log2(e)*c   =>  tanh(c) = 2/(1+2^cs) - 1 = 2r - 1.
__global__ void __launch_bounds__(NTHREADS, 1)
lstm_kernel(const float* __restrict__ x,
            const float* __restrict__ h0in,
            const float* __restrict__ c0in,
            const float* __restrict__ w_ih,
            const float* __restrict__ w_hh,
            const float* __restrict__ b_ih,
            const float* __restrict__ b_hh,
            float* __restrict__ out)
{
    const int tid  = blockIdx.x * NTHREADS + threadIdx.x;
    const int pair = tid >> 1;          // chain (batch element)
    const int u    = tid & 1;           // hidden unit owned by this lane
    const int v    = u ^ 1;             // partner's unit

    // Gate rows (torch order): i=0+u, f=2+u, g=4+u, o=6+u. q: 0=i,1=g,2=f,3=o
    // whO multiplies h_own (early), whX multiplies h_oth (late, outermost fma).
    float wi0[4], wi1[4], whO[4], whX[4], bs[4];
    const int qrow[4] = {0 + u, 4 + u, 2 + u, 6 + u};   // i, g, f, o
#pragma unroll
    for (int q = 0; q < 4; q++) {
        const int row = qrow[q];
        const float s = (q == 1) ? 1.0f : 0.5f;         // g unscaled
        wi0[q] = s * __ldg(&w_ih[2*row+0]);
        wi1[q] = s * __ldg(&w_ih[2*row+1]);
        whO[q] = s * __ldg(&w_hh[2*row+u]);
        whX[q] = s * __ldg(&w_hh[2*row+v]);
        bs[q]  = s * (__ldg(&b_ih[row]) + __ldg(&b_hh[row]));
    }

    float h_own = h0in[2*pair + u];
    float cs    = N2L2E * c0in[2*pair + u];   // scaled cell state
    float hcs   = 0.5f * cs;                  // running 0.5*cs (off path)

    const float4* __restrict__ xr =
        reinterpret_cast<const float4*>(x) + (size_t)pair * (TT * 2 / 4);

    float4 buf[2][CHUNK / 2];
#pragma unroll
    for (int q = 0; q < CHUNK / 2; q++) buf[0][q] = __ldg(&xr[q]);

#pragma unroll 1
    for (int ch = 0; ch < TT / CHUNK; ch++) {
        const int nb = (ch + 1) & 1;
        if (ch + 1 < TT / CHUNK) {
#pragma unroll
            for (int q = 0; q < CHUNK / 2; q++)
                buf[nb][q] = __ldg(&xr[(ch + 1) * (CHUNK / 2) + q]);
        }
#pragma unroll
        for (int s2 = 0; s2 < CHUNK / 2; s2++) {
            const float4 v4 = buf[ch & 1][s2];
#pragma unroll
            for (int half = 0; half < 2; half++) {
                const float x0 = half ? v4.z : v4.x;
                const float x1 = half ? v4.w : v4.y;

                // Single butterfly exchange; partner's h arrives last ->
                // keep it in the OUTERMOST fma of each gate.
                const float h_oth = __shfl_xor_sync(0xffffffffu, h_own, 1);

                float z[4];
#pragma unroll
                for (int q = 0; q < 4; q++) {
                    float t = fmaf(x1, wi1[q], bs[q]);
                    t = fmaf(x0, wi0[q], t);
                    t = fmaf(h_own, whO[q], t);
                    t = fmaf(h_oth, whX[q], t);
                    z[q] = t;
                }

                // Issue order i, g, f (c-path), then o.
                const float ti = tanh_ap(z[0]);
                const float tg = tanh_ap(z[1]);
                const float tf = tanh_ap(z[2]);
                const float to = tanh_ap(z[3]);

                // cs' = sigma(f)*cs + N2L2E*sigma(i)*tanh(g)
                //     = (hcs*tf + hcs) + si'*tg,  si' = NL2E*ti + NL2E
                const float sip = fmaf(NL2E, ti, NL2E);
                const float q0  = fmaf(sip, tg, hcs);
                cs = fmaf(hcs, tf, q0);

                // h' = sigma(o) * tanh(c') = (2r-1)*so,  r = 1/(1+2^cs)
                const float so     = fmaf(0.5f, to, 0.5f);
                const float two_so = so + so;                 // off path
                const float zc = fminf(fmaxf(cs, -60.0f), 60.0f);
                const float r  = sig2_fma(zc);
                h_own = fmaf(two_so, r, -so);

                hcs = 0.5f * cs;
            }
        }
    }

    out[2*pair + u] = cs * INVS;   // un-scale cell state once
}

extern "C" void kernel_launch(void* const* d_in, const int* in_sizes, int n_in,
                              void* d_out, int out_size) {
    const float* x    = (const float*)d_in[0];
    const float* h0   = (const float*)d_in[1];
    const float* c0   = (const float*)d_in[2];
    const float* w_ih = (const float*)d_in[3];
    const float* w_hh = (const float*)d_in[4];
    const float* b_ih = (const float*)d_in[5];
    const float* b_hh = (const float*)d_in[6];
    lstm_kernel<<<NBLOCKS, NTHREADS>>>(x, h0, c0, w_ih, w_hh, b_ih, b_hh,
                                       (float*)d_out);
}

// round 8
// speedup vs baseline: 1.3752x; 1.0089x over previous
#include <cuda_runtime.h>

#define BB 8192
#define TT 2048
#define NTHREADS 128   // 4 warps/block -> exactly 1 warp per SMSP
#define NBLOCKS  64    // 256 warps total, thread-per-chain
#define CHUNK 8        // timesteps per prefetch chunk (4 float4 per thread)

typedef unsigned long long u64;

__device__ __forceinline__ float tanh_ap(float x) {
    float y;
    asm("tanh.approx.f32 %0, %1;" : "=f"(y) : "f"(x));
    return y;
}
__device__ __forceinline__ u64 pk(float a, float b) {
    u64 r;
    asm("mov.b64 %0, {%1, %2};" : "=l"(r) : "f"(a), "f"(b));
    return r;
}
__device__ __forceinline__ void upk(float& a, float& b, u64 p) {
    asm("mov.b64 {%0, %1}, %2;" : "=f"(a), "=f"(b) : "l"(p));
}
// packed dual fp32 fma (FFMA2) — IEEE fma per lane; halves z-GEMV issue count
__device__ __forceinline__ u64 ffma2(u64 a, u64 b, u64 c) {
    u64 r;
    asm("fma.rn.f32x2 %0, %1, %2, %3;" : "=l"(r) : "l"(a), "l"(b), "l"(c));
    return r;
}

// Thread-per-chain, 1 warp/SMSP. Model (all HW-fit from R0..R6):
//   chain/step = z-fma 8 + tanh 58 + c-tree 12 + tanh 58 + mul 4 = 140 cyc
//   MUFU busy  = 10 TANH x rt16 = 160 cyc  (binding)
//   issue      = ~38 instr (FFMA2-packed) -> hides under MUFU/act waits
// -> period ~165-190 cyc vs 215 for the lane-pair (shfl on chain) variant.
__global__ void __launch_bounds__(NTHREADS, 1)
lstm_kernel(const float* __restrict__ x,
            const float* __restrict__ h0in,
            const float* __restrict__ c0in,
            const float* __restrict__ w_ih,
            const float* __restrict__ w_hh,
            const float* __restrict__ b_ih,
            const float* __restrict__ b_hh,
            float* __restrict__ out)
{
    const int b = blockIdx.x * NTHREADS + threadIdx.x;

    // Gate rows (torch order): [0,1]=i [2,3]=f [4,5]=g [6,7]=o.
    // sigma(z) = 0.5*tanh(0.5 z)+0.5 with the 0.5 folded into weights/bias.
    // Gate pairs p: z[2p], z[2p+1] packed in one f32x2 lane-pair.
    u64 WI0[4], WI1[4], WH0[4], WH1[4], BS[4];
#pragma unroll
    for (int p = 0; p < 4; p++) {
        const float s = (p == 2) ? 1.0f : 0.5f;   // pair 2 = g gates (tanh)
        const int k0 = 2 * p, k1 = 2 * p + 1;
        WI0[p] = pk(s * __ldg(&w_ih[2*k0+0]), s * __ldg(&w_ih[2*k1+0]));
        WI1[p] = pk(s * __ldg(&w_ih[2*k0+1]), s * __ldg(&w_ih[2*k1+1]));
        WH0[p] = pk(s * __ldg(&w_hh[2*k0+0]), s * __ldg(&w_hh[2*k1+0]));
        WH1[p] = pk(s * __ldg(&w_hh[2*k0+1]), s * __ldg(&w_hh[2*k1+1]));
        BS[p]  = pk(s * (__ldg(&b_ih[k0]) + __ldg(&b_hh[k0])),
                    s * (__ldg(&b_ih[k1]) + __ldg(&b_hh[k1])));
    }

    float h_0 = h0in[2*b+0], h_1 = h0in[2*b+1];
    float c_0 = c0in[2*b+0], c_1 = c0in[2*b+1];
    float hc0 = 0.5f * c_0,  hc1 = 0.5f * c_1;   // running 0.5*c (off path)

    const float4* __restrict__ xr =
        reinterpret_cast<const float4*>(x) + (size_t)b * (TT * 2 / 4);

    float4 buf[2][CHUNK / 2];
#pragma unroll
    for (int q = 0; q < CHUNK / 2; q++) buf[0][q] = __ldg(&xr[q]);

#pragma unroll 1
    for (int ch = 0; ch < TT / CHUNK; ch++) {
        const int nb = (ch + 1) & 1;
        if (ch + 1 < TT / CHUNK) {
#pragma unroll
            for (int q = 0; q < CHUNK / 2; q++)
                buf[nb][q] = __ldg(&xr[(ch + 1) * (CHUNK / 2) + q]);
        }
#pragma unroll
        for (int s2 = 0; s2 < CHUNK / 2; s2++) {
            const float4 v = buf[ch & 1][s2];
#pragma unroll
            for (int half = 0; half < 2; half++) {
                const float x0 = half ? v.z : v.x;
                const float x1 = half ? v.w : v.y;

                // x/bias partial — no h dependency, hoistable off the path.
                const u64 X0 = pk(x0, x0), X1 = pk(x1, x1);
                u64 P[4];
#pragma unroll
                for (int p = 0; p < 4; p++) {
                    u64 t = ffma2(X1, WI1[p], BS[p]);
                    P[p] = ffma2(X0, WI0[p], t);
                }

                // h-dependent tail: 2 packed fma deep from h.
                const u64 H0 = pk(h_0, h_0), H1 = pk(h_1, h_1);
#pragma unroll
                for (int p = 0; p < 4; p++) {
                    P[p] = ffma2(H1, WH1[p], P[p]);
                    P[p] = ffma2(H0, WH0[p], P[p]);
                }

                float z0, z1, z2, z3, z4, z5, z6, z7;
                upk(z0, z1, P[0]);
                upk(z2, z3, P[1]);
                upk(z4, z5, P[2]);
                upk(z6, z7, P[3]);

                const float ti0 = tanh_ap(z0), ti1 = tanh_ap(z1);
                const float tf0 = tanh_ap(z2), tf1 = tanh_ap(z3);
                const float tg0 = tanh_ap(z4), tg1 = tanh_ap(z5);
                const float to0 = tanh_ap(z6), to1 = tanh_ap(z7);

                const float si0 = fmaf(0.5f, ti0, 0.5f);
                const float si1 = fmaf(0.5f, ti1, 0.5f);
                const float so0 = fmaf(0.5f, to0, 0.5f);
                const float so1 = fmaf(0.5f, to1, 0.5f);

                // c' = (0.5c)*t_f + (0.5c + sigma(i)*t_g): one fma after tanh(f)
                const float q0 = fmaf(si0, tg0, hc0);
                const float q1 = fmaf(si1, tg1, hc1);
                c_0 = fmaf(hc0, tf0, q0);
                c_1 = fmaf(hc1, tf1, q1);

                const float tc0 = tanh_ap(c_0);
                const float tc1 = tanh_ap(c_1);
                h_0 = so0 * tc0;
                h_1 = so1 * tc1;
                hc0 = 0.5f * c_0;
                hc1 = 0.5f * c_1;
            }
        }
    }

    out[2*b+0] = c_0;
    out[2*b+1] = c_1;
}

extern "C" void kernel_launch(void* const* d_in, const int* in_sizes, int n_in,
                              void* d_out, int out_size) {
    const float* x    = (const float*)d_in[0];
    const float* h0   = (const float*)d_in[1];
    const float* c0   = (const float*)d_in[2];
    const float* w_ih = (const float*)d_in[3];
    const float* w_hh = (const float*)d_in[4];
    const float* b_ih = (const float*)d_in[5];
    const float* b_hh = (const float*)d_in[6];
    lstm_kernel<<<NBLOCKS, NTHREADS>>>(x, h0, c0, w_ih, w_hh, b_ih, b_hh,
                                       (float*)d_out);
}